// round 1
// baseline (speedup 1.0000x reference)
#include <cuda_runtime.h>
#include <math.h>

// Problem constants (fixed shapes from reference)
#define NCLS 22
#define NB   2
#define HH   480
#define WW   640
#define SKIP 8
#define HS   (HH/SKIP)      // 60
#define WS   (WW/SKIP)      // 80
#define PP   (HS*WS)        // 4800
#define EPSF 1e-8f

// Vote kernel tiling
#define JPB    32           // target points per block
#define ISPLIT 16           // i-loop split
#define ICHUNK (PP/ISPLIT)  // 300
#define VBLK   (JPB*ISPLIT) // 512 threads
#define NJB    (PP/JPB)     // 150 j-blocks per batch

// Scratch (allocation-free: __device__ globals)
__device__ float g_us[NB*PP];
__device__ float g_vs[NB*PP];
__device__ float g_zz[NB*PP];
__device__ int   g_lab[NB*PP];
__device__ int   g_key[NB*NCLS];

// ---------------------------------------------------------------------------
// Kernel 1: subsample + channel gather + direction pre-normalization.
// Also zeroes the packed argmax keys.
// ---------------------------------------------------------------------------
__global__ void hv_precompute(const int* __restrict__ lab2d,
                              const float* __restrict__ vp) {
    int t = blockIdx.x * blockDim.x + threadIdx.x;
    if (t < NB*NCLS) g_key[t] = 0;
    if (t >= NB*PP) return;
    int n = t / PP, p = t % PP;
    int r = p / WS, c = p % WS;
    int y = r * SKIP, x = c * SKIP;
    int lab = lab2d[(n*HH + y)*WW + x];
    const float* base = vp + (size_t)n * (3*NCLS) * HH * WW;
    size_t off = (size_t)(3*lab) * HH * WW + (size_t)y * WW + x;
    float u = base[off];
    float v = base[off + (size_t)HH*WW];
    float z = base[off + (size_t)2*HH*WW];
    float nrm = sqrtf(u*u + v*v) + EPSF;
    g_us[t] = u / nrm;
    g_vs[t] = v / nrm;
    g_zz[t] = z;
    g_lab[t] = lab;
}

// ---------------------------------------------------------------------------
// Kernel 2: O(P^2) voting. Block = 32 j's x 16 i-slices. SMEM hough[32][23],
// then per-class block argmax -> global atomicMax on packed (votes, j) key.
// Packing: key = (votes << 13) | (8191 - j). votes,j < 8192. Higher votes win;
// ties resolve to smallest j (== jnp.argmax first-max semantics).
// ---------------------------------------------------------------------------
__global__ void __launch_bounds__(VBLK) hv_vote() {
    __shared__ int sh[JPB * 23];  // stride 23: conflict-free (lab warp-uniform)
    int n  = blockIdx.x / NJB;
    int jb = blockIdx.x % NJB;
    int tid = threadIdx.x;
    int jt = tid & (JPB - 1);
    int is = tid >> 5;           // warp = fixed is -> i-data loads broadcast
    int j  = jb * JPB + jt;
    float pxj = (float)((j % WS) * SKIP);
    float pyj = (float)((j / WS) * SKIP);

    for (int k = tid; k < JPB*23; k += VBLK) sh[k] = 0;
    __syncthreads();

    const float* us = g_us + n*PP;
    const float* vs = g_vs + n*PP;
    const int*   lb = g_lab + n*PP;

    int i0 = is * ICHUNK;
    int ri = i0 / WS, ci = i0 % WS;
    for (int i = i0; i < i0 + ICHUNK; ++i) {
        int   labi = lb[i];
        float usi  = us[i];
        float vsi  = vs[i];
        float dx = pxj - (float)(ci * SKIP);
        float dy = pyj - (float)(ri * SKIP);
        ++ci; if (ci == WS) { ci = 0; ++ri; }
        float d2   = dx*dx + dy*dy;
        float dist = sqrtf(d2);
        float dot  = usi*dx + vsi*dy;
        if (labi > 0 && d2 > 0.0f && dot >= 0.9f*(dist + EPSF))
            atomicAdd(&sh[jt*23 + labi], 1);
    }
    __syncthreads();

    if (tid < NCLS) {
        int c = tid;
        int bestkey = 0;
        #pragma unroll
        for (int q = 0; q < JPB; ++q) {
            int v   = sh[q*23 + c];
            int jj  = jb*JPB + q;
            int key = (v << 13) | (8191 - jj);
            if (key > bestkey) bestkey = key;
        }
        atomicMax(&g_key[n*NCLS + c], bestkey);
    }
}

// ---------------------------------------------------------------------------
// Kernel 3: one block per (n, c). Decode best/max_votes, count labels,
// recompute inliers toward best center, emit top_box and top_pose rows.
// ---------------------------------------------------------------------------
__global__ void hv_finalize(const float* __restrict__ extents,
                            const float* __restrict__ meta,
                            float* __restrict__ out) {
    __shared__ int   s_cnt[256];
    __shared__ int   s_nin[256];
    __shared__ float s_zs[256];

    int n = blockIdx.x / NCLS;
    int c = blockIdx.x % NCLS;
    int tid = threadIdx.x;

    int key  = g_key[n*NCLS + c];
    int best = 8191 - (key & 8191);
    float mv = (float)(key >> 13);
    float pxb = (float)((best % WS) * SKIP);
    float pyb = (float)((best / WS) * SKIP);

    const float* us = g_us + n*PP;
    const float* vs = g_vs + n*PP;
    const float* zz = g_zz + n*PP;
    const int*   lb = g_lab + n*PP;

    int cnt = 0, nin = 0;
    float zs = 0.0f;
    for (int i = tid; i < PP; i += 256) {
        int labi = lb[i];
        if (labi != c) continue;
        ++cnt;
        if (labi > 0) {
            float dx = pxb - (float)((i % WS) * SKIP);
            float dy = pyb - (float)((i / WS) * SKIP);
            float d2 = dx*dx + dy*dy;
            float dist = sqrtf(d2);
            float dot  = us[i]*dx + vs[i]*dy;
            if (d2 > 0.0f && dot >= 0.9f*(dist + EPSF)) { ++nin; zs += zz[i]; }
        }
    }
    s_cnt[tid] = cnt; s_nin[tid] = nin; s_zs[tid] = zs;
    __syncthreads();
    for (int s = 128; s > 0; s >>= 1) {
        if (tid < s) {
            s_cnt[tid] += s_cnt[tid+s];
            s_nin[tid] += s_nin[tid+s];
            s_zs[tid]  += s_zs[tid+s];
        }
        __syncthreads();
    }

    if (tid == 0) {
        float count = (float)s_cnt[0];
        bool valid = (count * (float)(SKIP*SKIP) >= 500.0f) &&
                     (mv >= 10.0f) &&
                     (mv >= 0.02f * count) &&
                     (c > 0);
        float vmf = valid ? 1.0f : 0.0f;
        float zm = s_zs[0] / fmaxf((float)s_nin[0], 1.0f);
        float zc = fmaxf(zm, 0.001f);
        float fx  = meta[n*9 + 0];
        float ppx = meta[n*9 + 2];
        float fy  = meta[n*9 + 4];
        float ppy = meta[n*9 + 5];
        float bw = extents[c*3 + 0] * fx / zc;
        float bh = extents[c*3 + 1] * fy / zc;
        float cx = pxb, cy = pyb;

        float* tb = out + (n*NCLS + c)*7;
        tb[0] = (float)n * vmf;
        tb[1] = (float)c * vmf;
        tb[2] = (cx - bw*0.5f) * vmf;
        tb[3] = (cy - bh*0.5f) * vmf;
        tb[4] = (cx + bw*0.5f) * vmf;
        tb[5] = (cy + bh*0.5f) * vmf;
        tb[6] = mv * vmf;

        float tx = (cx - ppx) * zc / fx;
        float ty = (cy - ppy) * zc / fy;
        float* tp = out + NB*NCLS*7 + (n*NCLS + c)*7;
        tp[0] = vmf;
        tp[1] = 0.0f;
        tp[2] = 0.0f;
        tp[3] = 0.0f;
        tp[4] = tx * vmf;
        tp[5] = ty * vmf;
        tp[6] = zc * vmf;
    }
}

extern "C" void kernel_launch(void* const* d_in, const int* in_sizes, int n_in,
                              void* d_out, int out_size) {
    const int*   lab2d   = (const int*)d_in[0];
    const float* vp      = (const float*)d_in[1];
    const float* extents = (const float*)d_in[2];
    // d_in[3] = poses (unused by reference output)
    const float* meta    = (const float*)d_in[4];
    float* out = (float*)d_out;

    hv_precompute<<<(NB*PP + 255)/256, 256>>>(lab2d, vp);
    hv_vote<<<NB*NJB, VBLK>>>();
    hv_finalize<<<NB*NCLS, 256>>>(extents, meta, out);
}